// round 11
// baseline (speedup 1.0000x reference)
#include <cuda_runtime.h>

// Problem constants
#define BB 16
#define HH 768
#define WW 1280
#define PAD 4
#define IMG (HH * WW)
#define C4  (WW / 4)           // 320 float4 chunks per row
#define WPR (C4 / 64)          // 5 warp-units per row (each unit: 64 chunks)
#define NUNITS (BB * HH * WPR) // 61,440 warp-units

// Persistent grid geometry
#define NBLOCKS 1184           // 148 SMs x 8 blocks (one-wave capacity at 256thr)
#define NTHREADS 256
#define NWARPS (NBLOCKS * (NTHREADS / 32))   // 9472
// w += 9472 decomposition over (segi in 5, y in 768, b)
#define DSEG 2                 // 9472 % 5
#define DY   358               // (9472/5) - 2*768
#define DB   2

// out = (dsp*w + eps)/(w + eps) = dsp + eps*(1-dsp)/(w+eps)
// w in [0.1492, 0.1690] always  =>  |out - dsp| <= 6.7e-12 absolute.
// Interior output == estDisp shifted by (+4,+4), except where dsp ~ 0
// (exact zeros occur in uniform inputs; guarded by the min-check).
//
// Lane-dense mapping (every LDG/STG a 512B warp txn), persistent launch,
// .cs evict-first stores to protect est L2 residency across replays.
// R11: software pipelining — iteration k+1's est loads are issued BEFORE
// iteration k's min-check/stores, doubling in-flight loads per warp-slot
// and hiding load latency behind the emit work.

__device__ __forceinline__ void st4_cs(float* p, float4 v) {
    __stcs(reinterpret_cast<float4*>(p), v);
}

__device__ __forceinline__ float full_formula(const float* imgB, const float* estB,
                                              int y, int xi)
{
    const float dist = 0.16901332f;   // exp(-32/18)
    const float eps  = 1e-12f;
    float dsp = 0.0f;
    if (y >= PAD && xi >= PAD)
        dsp = estB[(y - PAD) * WW + (xi - PAD)];
    float c = imgB[y * WW + xi];
    float s = 0.0f;
    if (y + PAD < HH && xi + PAD < WW)
        s = imgB[(y + PAD) * WW + (xi + PAD)];
    float d = c - s;
    float w = dist * __expf(d * d * (-0.125f));
    return (dsp * w + eps) / (w + eps);
}

// exact path for one float4 chunk
__device__ __forceinline__ void slow_chunk(const float* imgB, const float* estB,
                                           float* outB, int y, int x)
{
    float r[4];
#pragma unroll
    for (int i = 0; i < 4; i++)
        r[i] = full_formula(imgB, estB, y, x + i);
    st4_cs(outB + y * WW + x, make_float4(r[0], r[1], r[2], r[3]));
}

__device__ __forceinline__ void emit_chunk(const float* imgB, const float* estB,
                                           float* outB, int y, int c, float4 d)
{
    float mn = fminf(fminf(d.x, d.y), fminf(d.z, d.w));
    if (mn >= 1e-5f) {
        st4_cs(outB + y * WW + c * 4, d);
    } else {
        slow_chunk(imgB, estB, outB, y, c * 4);   // rare tiny-dsp chunk
    }
}

__global__ __launch_bounds__(NTHREADS) void bilateral_kernel(
    const float* __restrict__ img,
    const float* __restrict__ est,
    float* __restrict__ out)
{
    const int lane = threadIdx.x & 31;
    int w = (blockIdx.x * NTHREADS + threadIdx.x) >> 5;   // warp-unit id

    // one-time decomposition
    int segi = w % WPR;
    int yb   = w / WPR;
    int y    = yb % HH;
    int b    = yb / HH;
    int c0   = segi * 64 + lane;

    // prologue: prefetch first iteration's loads
    float4 d0 = make_float4(0.f, 0.f, 0.f, 0.f);
    float4 d1 = make_float4(0.f, 0.f, 0.f, 0.f);
    bool valid = (w < NUNITS);
    bool fasty = valid && (y >= PAD);
    if (fasty) {
        const float4* erow =
            reinterpret_cast<const float4*>(est + b * IMG + (y - PAD) * WW);
        d1 = __ldg(erow + (c0 + 31));
        if (c0 >= 1) d0 = __ldg(erow + (c0 - 1));
    }

    while (valid) {
        // snapshot current iteration's state
        const int   cy = y, cb = b, cc0 = c0;
        const bool  cfast = fasty;
        const float4 cd0 = d0, cd1 = d1;

        // advance indices (w += NWARPS)
        w += NWARPS;
        valid = (w < NUNITS);
        segi += DSEG;
        int carry = 0;
        if (segi >= WPR) { segi -= WPR; carry = 1; }
        y += DY + carry;
        b += DB;
        if (y >= HH) { y -= HH; b += 1; }
        c0 = segi * 64 + lane;
        fasty = valid && (y >= PAD);

        // prefetch next iteration's loads (overlaps current emit below)
        if (fasty) {
            const float4* erow =
                reinterpret_cast<const float4*>(est + b * IMG + (y - PAD) * WW);
            d1 = __ldg(erow + (c0 + 31));
            if (c0 >= 1) d0 = __ldg(erow + (c0 - 1));
        }

        // emit current iteration
        const float* imgB = img + cb * IMG;
        const float* estB = est + cb * IMG;
        float*       outB = out + cb * IMG;
        if (cfast) {
            emit_chunk(imgB, estB, outB, cy, cc0 + 32, cd1);
            if (cc0 >= 1) emit_chunk(imgB, estB, outB, cy, cc0, cd0);
            else          slow_chunk(imgB, estB, outB, cy, 0);  // x==0 chunk
        } else {
            // top boundary rows: exact formula
            slow_chunk(imgB, estB, outB, cy, cc0 * 4);
            slow_chunk(imgB, estB, outB, cy, (cc0 + 32) * 4);
        }
    }
}

extern "C" void kernel_launch(void* const* d_in, const int* in_sizes, int n_in,
                              void* d_out, int out_size)
{
    const float* img = (const float*)d_in[0];   // leftImage
    const float* est = (const float*)d_in[1];   // estDisp
    float* out = (float*)d_out;

    bilateral_kernel<<<NBLOCKS, NTHREADS>>>(img, est, out);
}

// round 12
// speedup vs baseline: 1.1656x; 1.1656x over previous
#include <cuda_runtime.h>

// Problem constants
#define BB 16
#define HH 768
#define WW 1280
#define PAD 4
#define IMG (HH * WW)
#define C4  (WW / 4)           // 320 float4 chunks per row
#define WPR (C4 / 64)          // 5 warp-units per row (each unit: 64 chunks)
#define NUNITS (BB * HH * WPR) // 61,440 warp-units

#define NBLOCKS 1184           // 148 SMs x 8 resident blocks (one wave)
#define NTHREADS 256

// out = (dsp*w + eps)/(w + eps) = dsp + eps*(1-dsp)/(w+eps)
// w in [0.1492, 0.1690] always  =>  |out - dsp| <= 6.7e-12 absolute.
// Interior output == estDisp shifted by (+4,+4), except where dsp ~ 0
// (exact zeros occur in uniform inputs; guarded by the min-check).
//
// R9 structure (proven best): lane-dense mapping — every LDG/STG is a
// dense 512B warp transaction; persistent one-wave launch; .cs stores to
// keep the write-only output from evicting est in L2 across graph replays.
// R12 deltas: (a) the x-shift load is index-clamped and unconditional, so
// the two front loads issue back-to-back unpredicated (chunk 0 discards
// the clamped data via its mandatory slow path); (b) a single combined
// 8-way min and ONE divergence region per iteration instead of two.

__device__ __forceinline__ void st4_cs(float* p, float4 v) {
    __stcs(reinterpret_cast<float4*>(p), v);
}

__device__ __forceinline__ float full_formula(const float* imgB, const float* estB,
                                              int y, int xi)
{
    const float dist = 0.16901332f;   // exp(-32/18)
    const float eps  = 1e-12f;
    float dsp = 0.0f;
    if (y >= PAD && xi >= PAD)
        dsp = estB[(y - PAD) * WW + (xi - PAD)];
    float c = imgB[y * WW + xi];
    float s = 0.0f;
    if (y + PAD < HH && xi + PAD < WW)
        s = imgB[(y + PAD) * WW + (xi + PAD)];
    float d = c - s;
    float w = dist * __expf(d * d * (-0.125f));
    return (dsp * w + eps) / (w + eps);
}

// exact path for one float4 chunk
__device__ __forceinline__ void slow_chunk(const float* imgB, const float* estB,
                                           float* outB, int y, int x)
{
    float r[4];
#pragma unroll
    for (int i = 0; i < 4; i++)
        r[i] = full_formula(imgB, estB, y, x + i);
    st4_cs(outB + y * WW + x, make_float4(r[0], r[1], r[2], r[3]));
}

__device__ __forceinline__ void emit_chunk(const float* imgB, const float* estB,
                                           float* outB, int y, int c, float4 d)
{
    float mn = fminf(fminf(d.x, d.y), fminf(d.z, d.w));
    if (mn >= 1e-5f) {
        st4_cs(outB + y * WW + c * 4, d);
    } else {
        slow_chunk(imgB, estB, outB, y, c * 4);
    }
}

__global__ __launch_bounds__(NTHREADS, 8) void bilateral_kernel(
    const float* __restrict__ img,
    const float* __restrict__ est,
    float* __restrict__ out)
{
    const int lane   = threadIdx.x & 31;
    const int warp0  = (blockIdx.x * NTHREADS + threadIdx.x) >> 5;
    const int nwarps = NBLOCKS * (NTHREADS / 32);   // 9472

    for (int w = warp0; w < NUNITS; w += nwarps) {
        const int segi = w % WPR;                  // 0..4
        const int yb   = w / WPR;
        const int y    = yb % HH;
        const int b    = yb / HH;

        const int c0 = segi * 64 + lane;           // float4 chunk index in row
        const int c1 = c0 + 32;

        const float* imgB = img + b * IMG;
        const float* estB = est + b * IMG;
        float*       outB = out + b * IMG;

        if (y >= PAD) {
            const float4* erow =
                reinterpret_cast<const float4*>(estB + (y - PAD) * WW);
            // two back-to-back unpredicated dense loads (x-4 shift = chunk-1;
            // chunk 0's clamped load is discarded by its mandatory slow path)
            const int i0 = (c0 >= 1) ? (c0 - 1) : 0;
            float4 d1 = __ldg(erow + (c1 - 1));
            float4 d0 = __ldg(erow + i0);

            // single combined min-check, single divergence region
            float m0 = fminf(fminf(d0.x, d0.y), fminf(d0.z, d0.w));
            float m1 = fminf(fminf(d1.x, d1.y), fminf(d1.z, d1.w));
            bool fast = (fminf(m0, m1) >= 1e-5f) && (c0 >= 1);

            if (fast) {
                st4_cs(outB + y * WW + c0 * 4, d0);
                st4_cs(outB + y * WW + c1 * 4, d1);
            } else {
                // rare tiny-dsp chunks, or the x==0 chunk (lane 0, seg 0)
                emit_chunk(imgB, estB, outB, y, c1, d1);
                if (c0 >= 1) emit_chunk(imgB, estB, outB, y, c0, d0);
                else         slow_chunk(imgB, estB, outB, y, 0);
            }
        } else {
            // top boundary rows: exact formula
            slow_chunk(imgB, estB, outB, y, c0 * 4);
            slow_chunk(imgB, estB, outB, y, c1 * 4);
        }
    }
}

extern "C" void kernel_launch(void* const* d_in, const int* in_sizes, int n_in,
                              void* d_out, int out_size)
{
    const float* img = (const float*)d_in[0];   // leftImage
    const float* est = (const float*)d_in[1];   // estDisp
    float* out = (float*)d_out;

    bilateral_kernel<<<NBLOCKS, NTHREADS>>>(img, est, out);
}